// round 2
// baseline (speedup 1.0000x reference)
#include <cuda_runtime.h>
#include <cuda_bf16.h>

#define NN 50000
#define EE 800000
#define F  128
#define NPAD 132   // padded row stride (floats) for conflict-free LDS

// ---------------- scratch (static device allocations, allowed) ----------------
__device__ int   g_cnt[NN];
__device__ int   g_fill[NN];
__device__ int   g_rowptr[NN + 1];
__device__ int   g_csrc[EE];
__device__ float g_cew[EE];
__device__ float g_neigh[(size_t)NN * F];
__device__ float g_h1[(size_t)NN * F];
__device__ float g_h2[(size_t)NN * F];

// ---------------- CSR build ----------------
__global__ void k_zero() {
    int i = blockIdx.x * blockDim.x + threadIdx.x;
    if (i < NN) { g_cnt[i] = 0; g_fill[i] = 0; }
}

__global__ void k_hist(const int* __restrict__ dst) {
    int e = blockIdx.x * blockDim.x + threadIdx.x;
    if (e < EE) atomicAdd(&g_cnt[dst[e]], 1);
}

// single-block chunked Hillis-Steele scan (exclusive prefix over g_cnt)
__global__ void k_scan() {
    __shared__ int sh[1024];
    const int tid = threadIdx.x;
    int carry = 0;
    for (int base = 0; base < NN; base += 1024) {
        int idx = base + tid;
        int x = (idx < NN) ? g_cnt[idx] : 0;
        int orig = x;
        sh[tid] = x; __syncthreads();
        for (int off = 1; off < 1024; off <<= 1) {
            int y = (tid >= off) ? sh[tid - off] : 0;
            __syncthreads();
            sh[tid] += y; __syncthreads();
        }
        if (idx < NN) g_rowptr[idx] = carry + sh[tid] - orig;
        carry += sh[1023];
        __syncthreads();
    }
    if (tid == 0) g_rowptr[NN] = carry;
}

__global__ void k_scatter(const int* __restrict__ src, const int* __restrict__ dst,
                          const float* __restrict__ ew) {
    int e = blockIdx.x * blockDim.x + threadIdx.x;
    if (e < EE) {
        int d = dst[e];
        int p = g_rowptr[d] + atomicAdd(&g_fill[d], 1);
        g_csrc[p] = src[e];
        g_cew[p]  = ew[e];
    }
}

// ---------------- neighbor mean aggregation (gather, warp per node) ----------------
__global__ void k_agg(const float* __restrict__ hin) {
    int v    = (blockIdx.x * blockDim.x + threadIdx.x) >> 5;
    int lane = threadIdx.x & 31;
    if (v >= NN) return;
    int s0 = g_rowptr[v], s1 = g_rowptr[v + 1];
    float4 acc = make_float4(0.f, 0.f, 0.f, 0.f);
    int i = s0;
    for (; i + 1 < s1; i += 2) {
        int   sa = g_csrc[i],     sb = g_csrc[i + 1];
        float wa = g_cew[i],      wb = g_cew[i + 1];
        const float4 A = *reinterpret_cast<const float4*>(hin + (size_t)sa * F + lane * 4);
        const float4 B = *reinterpret_cast<const float4*>(hin + (size_t)sb * F + lane * 4);
        acc.x += wa * A.x + wb * B.x;
        acc.y += wa * A.y + wb * B.y;
        acc.z += wa * A.z + wb * B.z;
        acc.w += wa * A.w + wb * B.w;
    }
    if (i < s1) {
        int   s  = g_csrc[i];
        float wt = g_cew[i];
        const float4 hv = *reinterpret_cast<const float4*>(hin + (size_t)s * F + lane * 4);
        acc.x += wt * hv.x; acc.y += wt * hv.y;
        acc.z += wt * hv.z; acc.w += wt * hv.w;
    }
    int deg = s1 - s0;
    float invd = 1.0f / (float)(deg > 1 ? deg : 1);
    acc.x *= invd; acc.y *= invd; acc.z *= invd; acc.w *= invd;
    *reinterpret_cast<float4*>(g_neigh + (size_t)v * F + lane * 4) = acc;
}

// ---------------- fused SAGE GEMM: out = relu(h@Ws + neigh@Wn + b) ----------------
// 256 threads; block tile = 32 nodes x 128 features. Each thread owns a
// 4-node x 4-feature register tile. Warp layout: ng = tid>>5 (whole warp shares
// the node group -> h/n LDS are warp-uniform broadcasts), jg = tid&31 (feature
// group -> stores are STG.128 coalesced). Weights transposed+padded in smem.
template <bool HN>
__global__ void __launch_bounds__(256, 1)
k_sage(const float* __restrict__ hin, const float* __restrict__ ws,
       const float* __restrict__ wn, const float* __restrict__ b,
       float* __restrict__ hout) {
    extern __shared__ float sm[];
    float* s_ws = sm;                      // [128][NPAD] transposed: s_ws[j*NPAD+k]
    float* s_wn = sm + F * NPAD;           // [128][NPAD]
    float* s_h  = sm + 2 * F * NPAD;       // [32][NPAD]
    float* s_n  = s_h + 32 * NPAD;         // [32][NPAD]

    const int tid = threadIdx.x;
    const int nodeBase = blockIdx.x * 32;

    // load + transpose weights (w[k][j] -> s[j*NPAD + k])
    for (int i = tid; i < F * F / 4; i += 256) {
        int k  = i >> 5;
        int j4 = (i & 31) * 4;
        float4 v = reinterpret_cast<const float4*>(ws)[i];
        s_ws[(j4 + 0) * NPAD + k] = v.x;
        s_ws[(j4 + 1) * NPAD + k] = v.y;
        s_ws[(j4 + 2) * NPAD + k] = v.z;
        s_ws[(j4 + 3) * NPAD + k] = v.w;
        if (HN) {
            float4 u = reinterpret_cast<const float4*>(wn)[i];
            s_wn[(j4 + 0) * NPAD + k] = u.x;
            s_wn[(j4 + 1) * NPAD + k] = u.y;
            s_wn[(j4 + 2) * NPAD + k] = u.z;
            s_wn[(j4 + 3) * NPAD + k] = u.w;
        }
    }

    // load node tile (32 nodes x 128 feats) for h and neigh
    for (int i = tid; i < 32 * 32; i += 256) {
        int n  = i >> 5;
        int kq = (i & 31) * 4;
        int v  = nodeBase + n;
        float4 hv = make_float4(0.f, 0.f, 0.f, 0.f);
        float4 nv = make_float4(0.f, 0.f, 0.f, 0.f);
        if (v < NN) {
            hv = *reinterpret_cast<const float4*>(hin + (size_t)v * F + kq);
            if (HN) nv = *reinterpret_cast<const float4*>(g_neigh + (size_t)v * F + kq);
        }
        *reinterpret_cast<float4*>(s_h + n * NPAD + kq) = hv;
        if (HN) *reinterpret_cast<float4*>(s_n + n * NPAD + kq) = nv;
    }
    __syncthreads();

    const int ng = tid >> 5;      // 0..7  -> nodes   4*ng .. 4*ng+3
    const int jg = tid & 31;      // 0..31 -> features 4*jg .. 4*jg+3
    const int n0 = 4 * ng;
    const int j0 = 4 * jg;

    float4 bv = *reinterpret_cast<const float4*>(b + j0);
    float acc[4][4];
#pragma unroll
    for (int i = 0; i < 4; i++) {
        acc[i][0] = bv.x; acc[i][1] = bv.y; acc[i][2] = bv.z; acc[i][3] = bv.w;
    }

    const float* h0 = s_h + (n0 + 0) * NPAD;
    const float* h1 = s_h + (n0 + 1) * NPAD;
    const float* h2 = s_h + (n0 + 2) * NPAD;
    const float* h3 = s_h + (n0 + 3) * NPAD;
    const float* w0 = s_ws + (j0 + 0) * NPAD;
    const float* w1 = s_ws + (j0 + 1) * NPAD;
    const float* w2 = s_ws + (j0 + 2) * NPAD;
    const float* w3 = s_ws + (j0 + 3) * NPAD;

#pragma unroll 2
    for (int k = 0; k < F; k += 4) {
        float4 ha = *reinterpret_cast<const float4*>(h0 + k);
        float4 hb = *reinterpret_cast<const float4*>(h1 + k);
        float4 hc = *reinterpret_cast<const float4*>(h2 + k);
        float4 hd = *reinterpret_cast<const float4*>(h3 + k);
        float4 wa = *reinterpret_cast<const float4*>(w0 + k);
        float4 wb = *reinterpret_cast<const float4*>(w1 + k);
        float4 wc = *reinterpret_cast<const float4*>(w2 + k);
        float4 wd = *reinterpret_cast<const float4*>(w3 + k);

        acc[0][0] += ha.x*wa.x + ha.y*wa.y + ha.z*wa.z + ha.w*wa.w;
        acc[0][1] += ha.x*wb.x + ha.y*wb.y + ha.z*wb.z + ha.w*wb.w;
        acc[0][2] += ha.x*wc.x + ha.y*wc.y + ha.z*wc.z + ha.w*wc.w;
        acc[0][3] += ha.x*wd.x + ha.y*wd.y + ha.z*wd.z + ha.w*wd.w;
        acc[1][0] += hb.x*wa.x + hb.y*wa.y + hb.z*wa.z + hb.w*wa.w;
        acc[1][1] += hb.x*wb.x + hb.y*wb.y + hb.z*wb.z + hb.w*wb.w;
        acc[1][2] += hb.x*wc.x + hb.y*wc.y + hb.z*wc.z + hb.w*wc.w;
        acc[1][3] += hb.x*wd.x + hb.y*wd.y + hb.z*wd.z + hb.w*wd.w;
        acc[2][0] += hc.x*wa.x + hc.y*wa.y + hc.z*wa.z + hc.w*wa.w;
        acc[2][1] += hc.x*wb.x + hc.y*wb.y + hc.z*wb.z + hc.w*wb.w;
        acc[2][2] += hc.x*wc.x + hc.y*wc.y + hc.z*wc.z + hc.w*wc.w;
        acc[2][3] += hc.x*wd.x + hc.y*wd.y + hc.z*wd.z + hc.w*wd.w;
        acc[3][0] += hd.x*wa.x + hd.y*wa.y + hd.z*wa.z + hd.w*wa.w;
        acc[3][1] += hd.x*wb.x + hd.y*wb.y + hd.z*wb.z + hd.w*wb.w;
        acc[3][2] += hd.x*wc.x + hd.y*wc.y + hd.z*wc.z + hd.w*wc.w;
        acc[3][3] += hd.x*wd.x + hd.y*wd.y + hd.z*wd.z + hd.w*wd.w;

        if (HN) {
            float4 na = *reinterpret_cast<const float4*>(s_n + (n0 + 0) * NPAD + k);
            float4 nb = *reinterpret_cast<const float4*>(s_n + (n0 + 1) * NPAD + k);
            float4 nc = *reinterpret_cast<const float4*>(s_n + (n0 + 2) * NPAD + k);
            float4 nd = *reinterpret_cast<const float4*>(s_n + (n0 + 3) * NPAD + k);
            float4 ua = *reinterpret_cast<const float4*>(s_wn + (j0 + 0) * NPAD + k);
            float4 ub = *reinterpret_cast<const float4*>(s_wn + (j0 + 1) * NPAD + k);
            float4 uc = *reinterpret_cast<const float4*>(s_wn + (j0 + 2) * NPAD + k);
            float4 ud = *reinterpret_cast<const float4*>(s_wn + (j0 + 3) * NPAD + k);

            acc[0][0] += na.x*ua.x + na.y*ua.y + na.z*ua.z + na.w*ua.w;
            acc[0][1] += na.x*ub.x + na.y*ub.y + na.z*ub.z + na.w*ub.w;
            acc[0][2] += na.x*uc.x + na.y*uc.y + na.z*uc.z + na.w*uc.w;
            acc[0][3] += na.x*ud.x + na.y*ud.y + na.z*ud.z + na.w*ud.w;
            acc[1][0] += nb.x*ua.x + nb.y*ua.y + nb.z*ua.z + nb.w*ua.w;
            acc[1][1] += nb.x*ub.x + nb.y*ub.y + nb.z*ub.z + nb.w*ub.w;
            acc[1][2] += nb.x*uc.x + nb.y*uc.y + nb.z*uc.z + nb.w*uc.w;
            acc[1][3] += nb.x*ud.x + nb.y*ud.y + nb.z*ud.z + nb.w*ud.w;
            acc[2][0] += nc.x*ua.x + nc.y*ua.y + nc.z*ua.z + nc.w*ua.w;
            acc[2][1] += nc.x*ub.x + nc.y*ub.y + nc.z*ub.z + nc.w*ub.w;
            acc[2][2] += nc.x*uc.x + nc.y*uc.y + nc.z*uc.z + nc.w*uc.w;
            acc[2][3] += nc.x*ud.x + nc.y*ud.y + nc.z*ud.z + nc.w*ud.w;
            acc[3][0] += nd.x*ua.x + nd.y*ua.y + nd.z*ua.z + nd.w*ua.w;
            acc[3][1] += nd.x*ub.x + nd.y*ub.y + nd.z*ub.z + nd.w*ub.w;
            acc[3][2] += nd.x*uc.x + nd.y*uc.y + nd.z*uc.z + nd.w*uc.w;
            acc[3][3] += nd.x*ud.x + nd.y*ud.y + nd.z*ud.z + nd.w*ud.w;
        }
    }

#pragma unroll
    for (int i = 0; i < 4; i++) {
        int v = nodeBase + n0 + i;
        if (v < NN) {
            float4 o;
            o.x = fmaxf(acc[i][0], 0.f);
            o.y = fmaxf(acc[i][1], 0.f);
            o.z = fmaxf(acc[i][2], 0.f);
            o.w = fmaxf(acc[i][3], 0.f);
            *reinterpret_cast<float4*>(hout + (size_t)v * F + j0) = o;
        }
    }
}

// ---------------- final projection: out[v] = h[v] . w2 + b2 ----------------
__global__ void k_dot(const float* __restrict__ h, const float* __restrict__ w2,
                      const float* __restrict__ b2, float* __restrict__ out) {
    int v    = (blockIdx.x * blockDim.x + threadIdx.x) >> 5;
    int lane = threadIdx.x & 31;
    if (v >= NN) return;
    float4 hv = *reinterpret_cast<const float4*>(h + (size_t)v * F + lane * 4);
    float4 wv = *reinterpret_cast<const float4*>(w2 + lane * 4);
    float s = hv.x * wv.x + hv.y * wv.y + hv.z * wv.z + hv.w * wv.w;
#pragma unroll
    for (int o = 16; o; o >>= 1) s += __shfl_xor_sync(0xffffffffu, s, o);
    if (lane == 0) out[v] = s + b2[0];
}

// ---------------- launch ----------------
extern "C" void kernel_launch(void* const* d_in, const int* in_sizes, int n_in,
                              void* d_out, int out_size) {
    const float* inputs = (const float*)d_in[0];
    const float* ew     = (const float*)d_in[1];
    const int*   src    = (const int*)d_in[2];
    const int*   dst    = (const int*)d_in[3];
    const float* ws1 = (const float*)d_in[4];
    const float* wn1 = (const float*)d_in[5];
    const float* b1  = (const float*)d_in[6];
    const float* ws2 = (const float*)d_in[7];
    const float* wn2 = (const float*)d_in[8];
    const float* b2  = (const float*)d_in[9];
    const float* ws3 = (const float*)d_in[10];
    const float* wn3 = (const float*)d_in[11];
    const float* b3  = (const float*)d_in[12];
    const float* wl1 = (const float*)d_in[13];
    const float* bl1 = (const float*)d_in[14];
    const float* wl2 = (const float*)d_in[15];
    const float* bl2 = (const float*)d_in[16];
    float* out = (float*)d_out;

    float *h1, *h2;
    cudaGetSymbolAddress((void**)&h1, g_h1);
    cudaGetSymbolAddress((void**)&h2, g_h2);

    // smem: 2 weight tiles [128][NPAD] + 2 node tiles [32][NPAD]
    const size_t smem = (size_t)(2 * F * NPAD + 2 * 32 * NPAD) * sizeof(float); // 168960 B
    cudaFuncSetAttribute(k_sage<true>,  cudaFuncAttributeMaxDynamicSharedMemorySize, (int)smem);
    cudaFuncSetAttribute(k_sage<false>, cudaFuncAttributeMaxDynamicSharedMemorySize, (int)smem);

    const int TB = 256;
    // CSR build (once per launch; reused by all 3 layers)
    k_zero<<<(NN + TB - 1) / TB, TB>>>();
    k_hist<<<(EE + TB - 1) / TB, TB>>>(dst);
    k_scan<<<1, 1024>>>();
    k_scatter<<<(EE + TB - 1) / TB, TB>>>(src, dst, ew);

    const int aggBlocks  = (NN * 32 + TB - 1) / TB;   // warp per node
    const int sageBlocks = (NN + 31) / 32;            // 32 nodes per block

    // layer 1: inputs -> h1
    k_agg<<<aggBlocks, TB>>>(inputs);
    k_sage<true><<<sageBlocks, 256, smem>>>(inputs, ws1, wn1, b1, h1);
    // layer 2: h1 -> h2
    k_agg<<<aggBlocks, TB>>>(h1);
    k_sage<true><<<sageBlocks, 256, smem>>>(h1, ws2, wn2, b2, h2);
    // layer 3: h2 -> h1
    k_agg<<<aggBlocks, TB>>>(h2);
    k_sage<true><<<sageBlocks, 256, smem>>>(h2, ws3, wn3, b3, h1);
    // lin1: h1 -> h2 (self path only, relu)
    k_sage<false><<<sageBlocks, 256, smem>>>(h1, wl1, nullptr, bl1, h2);
    // lin2: h2 -> out
    k_dot<<<aggBlocks, TB>>>(h2, wl2, bl2, out);
}

// round 3
// speedup vs baseline: 2.3109x; 2.3109x over previous
#include <cuda_runtime.h>
#include <cuda_bf16.h>

#define NN 50000
#define EE 800000
#define F  128

// ---------------- scratch (static device allocations, allowed) ----------------
__device__ int   g_cnt[NN];
__device__ int   g_fill[NN];
__device__ int   g_rowptr[NN + 1];
__device__ int   g_csrc[EE];
__device__ float g_cew[EE];
__device__ float g_neigh[(size_t)NN * F];
__device__ float g_h1[(size_t)NN * F];
__device__ float g_h2[(size_t)NN * F];

// ---------------- CSR build ----------------
__global__ void k_zero() {
    int i = blockIdx.x * blockDim.x + threadIdx.x;
    if (i < NN) { g_cnt[i] = 0; g_fill[i] = 0; }
}

__global__ void k_hist(const int* __restrict__ dst) {
    int e = blockIdx.x * blockDim.x + threadIdx.x;
    if (e < EE) atomicAdd(&g_cnt[dst[e]], 1);
}

// single-block chunked Hillis-Steele scan (exclusive prefix over g_cnt)
__global__ void k_scan() {
    __shared__ int sh[1024];
    const int tid = threadIdx.x;
    int carry = 0;
    for (int base = 0; base < NN; base += 1024) {
        int idx = base + tid;
        int x = (idx < NN) ? g_cnt[idx] : 0;
        int orig = x;
        sh[tid] = x; __syncthreads();
        for (int off = 1; off < 1024; off <<= 1) {
            int y = (tid >= off) ? sh[tid - off] : 0;
            __syncthreads();
            sh[tid] += y; __syncthreads();
        }
        if (idx < NN) g_rowptr[idx] = carry + sh[tid] - orig;
        carry += sh[1023];
        __syncthreads();
    }
    if (tid == 0) g_rowptr[NN] = carry;
}

__global__ void k_scatter(const int* __restrict__ src, const int* __restrict__ dst,
                          const float* __restrict__ ew) {
    int e = blockIdx.x * blockDim.x + threadIdx.x;
    if (e < EE) {
        int d = dst[e];
        int p = g_rowptr[d] + atomicAdd(&g_fill[d], 1);
        g_csrc[p] = src[e];
        g_cew[p]  = ew[e];
    }
}

// ---------------- neighbor mean aggregation (gather, warp per node) ----------------
__global__ void k_agg(const float* __restrict__ hin) {
    int v    = (blockIdx.x * blockDim.x + threadIdx.x) >> 5;
    int lane = threadIdx.x & 31;
    if (v >= NN) return;
    int s0 = g_rowptr[v], s1 = g_rowptr[v + 1];
    float4 acc = make_float4(0.f, 0.f, 0.f, 0.f);
    int i = s0;
    for (; i + 1 < s1; i += 2) {
        int   sa = g_csrc[i],     sb = g_csrc[i + 1];
        float wa = g_cew[i],      wb = g_cew[i + 1];
        const float4 A = *reinterpret_cast<const float4*>(hin + (size_t)sa * F + lane * 4);
        const float4 B = *reinterpret_cast<const float4*>(hin + (size_t)sb * F + lane * 4);
        acc.x += wa * A.x + wb * B.x;
        acc.y += wa * A.y + wb * B.y;
        acc.z += wa * A.z + wb * B.z;
        acc.w += wa * A.w + wb * B.w;
    }
    if (i < s1) {
        int   s  = g_csrc[i];
        float wt = g_cew[i];
        const float4 hv = *reinterpret_cast<const float4*>(hin + (size_t)s * F + lane * 4);
        acc.x += wt * hv.x; acc.y += wt * hv.y;
        acc.z += wt * hv.z; acc.w += wt * hv.w;
    }
    int deg = s1 - s0;
    float invd = 1.0f / (float)(deg > 1 ? deg : 1);
    acc.x *= invd; acc.y *= invd; acc.z *= invd; acc.w *= invd;
    *reinterpret_cast<float4*>(g_neigh + (size_t)v * F + lane * 4) = acc;
}

// ---------------- fused SAGE GEMM: out = relu(h@Ws + neigh@Wn + b) ----------------
// 512 threads; block tile = 64 nodes x 128 features. Each thread owns a
// 4-node x 4-feature register tile.
//   warp  = tid>>5 -> node group (whole warp shares nodes -> h/n LDS broadcast)
//   lane  = tid&31 -> feature group j0 = 4*lane (weight LDS lane stride = 4
//                     banks -> conflict-free; stores STG.128 coalesced)
// Weights kept K-major (as in gmem): s_w[k*F + j]. No transpose, no padding.
template <bool HN>
__global__ void __launch_bounds__(512, 1)
k_sage(const float* __restrict__ hin, const float* __restrict__ ws,
       const float* __restrict__ wn, const float* __restrict__ b,
       float* __restrict__ hout) {
    extern __shared__ float sm[];
    float* s_ws = sm;                 // [128][128] K-major
    float* s_wn = sm + F * F;         // [128][128]
    float* s_h  = sm + 2 * F * F;     // [64][128]
    float* s_n  = s_h + 64 * F;       // [64][128]

    const int tid = threadIdx.x;
    const int nodeBase = blockIdx.x * 64;

    // copy weights straight (same layout; fully coalesced float4)
    for (int i = tid; i < F * F / 4; i += 512) {
        reinterpret_cast<float4*>(s_ws)[i] = reinterpret_cast<const float4*>(ws)[i];
        if (HN)
            reinterpret_cast<float4*>(s_wn)[i] = reinterpret_cast<const float4*>(wn)[i];
    }

    // load node tile (64 nodes x 128 feats) for h and neigh
    for (int i = tid; i < 64 * 32; i += 512) {
        int n  = i >> 5;
        int kq = (i & 31) * 4;
        int v  = nodeBase + n;
        float4 hv = make_float4(0.f, 0.f, 0.f, 0.f);
        float4 nv = make_float4(0.f, 0.f, 0.f, 0.f);
        if (v < NN) {
            hv = *reinterpret_cast<const float4*>(hin + (size_t)v * F + kq);
            if (HN) nv = *reinterpret_cast<const float4*>(g_neigh + (size_t)v * F + kq);
        }
        *reinterpret_cast<float4*>(s_h + n * F + kq) = hv;
        if (HN) *reinterpret_cast<float4*>(s_n + n * F + kq) = nv;
    }
    __syncthreads();

    const int n0 = 4 * (tid >> 5);    // node group (warp-uniform)
    const int j0 = 4 * (tid & 31);    // feature group

    float4 bv = *reinterpret_cast<const float4*>(b + j0);
    float acc[4][4];
#pragma unroll
    for (int i = 0; i < 4; i++) {
        acc[i][0] = bv.x; acc[i][1] = bv.y; acc[i][2] = bv.z; acc[i][3] = bv.w;
    }

#pragma unroll 2
    for (int k = 0; k < F; k += 4) {
        // h / n chunk values: broadcast LDS (warp-uniform addresses)
        float hreg[4][4], nreg[4][4];
#pragma unroll
        for (int i = 0; i < 4; i++) {
            float4 hv = *reinterpret_cast<const float4*>(s_h + (n0 + i) * F + k);
            hreg[i][0] = hv.x; hreg[i][1] = hv.y; hreg[i][2] = hv.z; hreg[i][3] = hv.w;
            if (HN) {
                float4 nv = *reinterpret_cast<const float4*>(s_n + (n0 + i) * F + k);
                nreg[i][0] = nv.x; nreg[i][1] = nv.y; nreg[i][2] = nv.z; nreg[i][3] = nv.w;
            }
        }
#pragma unroll
        for (int kk = 0; kk < 4; kk++) {
            float4 wk = *reinterpret_cast<const float4*>(s_ws + (k + kk) * F + j0);
#pragma unroll
            for (int i = 0; i < 4; i++) {
                float hv = hreg[i][kk];
                acc[i][0] += hv * wk.x;
                acc[i][1] += hv * wk.y;
                acc[i][2] += hv * wk.z;
                acc[i][3] += hv * wk.w;
            }
            if (HN) {
                float4 uk = *reinterpret_cast<const float4*>(s_wn + (k + kk) * F + j0);
#pragma unroll
                for (int i = 0; i < 4; i++) {
                    float nv = nreg[i][kk];
                    acc[i][0] += nv * uk.x;
                    acc[i][1] += nv * uk.y;
                    acc[i][2] += nv * uk.z;
                    acc[i][3] += nv * uk.w;
                }
            }
        }
    }

#pragma unroll
    for (int i = 0; i < 4; i++) {
        int v = nodeBase + n0 + i;
        if (v < NN) {
            float4 o;
            o.x = fmaxf(acc[i][0], 0.f);
            o.y = fmaxf(acc[i][1], 0.f);
            o.z = fmaxf(acc[i][2], 0.f);
            o.w = fmaxf(acc[i][3], 0.f);
            *reinterpret_cast<float4*>(hout + (size_t)v * F + j0) = o;
        }
    }
}

// ---------------- final projection: out[v] = h[v] . w2 + b2 ----------------
__global__ void k_dot(const float* __restrict__ h, const float* __restrict__ w2,
                      const float* __restrict__ b2, float* __restrict__ out) {
    int v    = (blockIdx.x * blockDim.x + threadIdx.x) >> 5;
    int lane = threadIdx.x & 31;
    if (v >= NN) return;
    float4 hv = *reinterpret_cast<const float4*>(h + (size_t)v * F + lane * 4);
    float4 wv = *reinterpret_cast<const float4*>(w2 + lane * 4);
    float s = hv.x * wv.x + hv.y * wv.y + hv.z * wv.z + hv.w * wv.w;
#pragma unroll
    for (int o = 16; o; o >>= 1) s += __shfl_xor_sync(0xffffffffu, s, o);
    if (lane == 0) out[v] = s + b2[0];
}

// ---------------- launch ----------------
extern "C" void kernel_launch(void* const* d_in, const int* in_sizes, int n_in,
                              void* d_out, int out_size) {
    const float* inputs = (const float*)d_in[0];
    const float* ew     = (const float*)d_in[1];
    const int*   src    = (const int*)d_in[2];
    const int*   dst    = (const int*)d_in[3];
    const float* ws1 = (const float*)d_in[4];
    const float* wn1 = (const float*)d_in[5];
    const float* b1  = (const float*)d_in[6];
    const float* ws2 = (const float*)d_in[7];
    const float* wn2 = (const float*)d_in[8];
    const float* b2  = (const float*)d_in[9];
    const float* ws3 = (const float*)d_in[10];
    const float* wn3 = (const float*)d_in[11];
    const float* b3  = (const float*)d_in[12];
    const float* wl1 = (const float*)d_in[13];
    const float* bl1 = (const float*)d_in[14];
    const float* wl2 = (const float*)d_in[15];
    const float* bl2 = (const float*)d_in[16];
    float* out = (float*)d_out;

    float *h1, *h2;
    cudaGetSymbolAddress((void**)&h1, g_h1);
    cudaGetSymbolAddress((void**)&h2, g_h2);

    // smem: 2 weight tiles [128][128] + 2 node tiles [64][128] = 192 KB
    const size_t smem = (size_t)(2 * F * F + 2 * 64 * F) * sizeof(float);
    cudaFuncSetAttribute(k_sage<true>,  cudaFuncAttributeMaxDynamicSharedMemorySize, (int)smem);
    cudaFuncSetAttribute(k_sage<false>, cudaFuncAttributeMaxDynamicSharedMemorySize, (int)smem);

    const int TB = 256;
    // CSR build (once per launch; reused by all 3 layers)
    k_zero<<<(NN + TB - 1) / TB, TB>>>();
    k_hist<<<(EE + TB - 1) / TB, TB>>>(dst);
    k_scan<<<1, 1024>>>();
    k_scatter<<<(EE + TB - 1) / TB, TB>>>(src, dst, ew);

    const int aggBlocks  = (NN * 32 + TB - 1) / TB;   // warp per node
    const int sageBlocks = (NN + 63) / 64;            // 64 nodes per block

    // layer 1: inputs -> h1
    k_agg<<<aggBlocks, TB>>>(inputs);
    k_sage<true><<<sageBlocks, 512, smem>>>(inputs, ws1, wn1, b1, h1);
    // layer 2: h1 -> h2
    k_agg<<<aggBlocks, TB>>>(h1);
    k_sage<true><<<sageBlocks, 512, smem>>>(h1, ws2, wn2, b2, h2);
    // layer 3: h2 -> h1
    k_agg<<<aggBlocks, TB>>>(h2);
    k_sage<true><<<sageBlocks, 512, smem>>>(h2, ws3, wn3, b3, h1);
    // lin1: h1 -> h2 (self path only, relu)
    k_sage<false><<<sageBlocks, 512, smem>>>(h1, wl1, nullptr, bl1, h2);
    // lin2: h2 -> out
    k_dot<<<aggBlocks, TB>>>(h2, wl2, bl2, out);
}

// round 6
// speedup vs baseline: 2.7304x; 1.1816x over previous
#include <cuda_runtime.h>
#include <cstdint>

#define NN 50000
#define EE 800000
#define F  128
#define WPAD 132            // transposed-weight row stride (floats): conflict-free

// ================= scratch =================
__device__ int   g_cnt[NN];
__device__ int   g_fill[NN];
__device__ int   g_rowptr[NN + 1];
__device__ int   g_csrc[EE];
__device__ float g_cew[EE];
__device__ float g_neigh[(size_t)NN * F];
__device__ float g_h1[(size_t)NN * F];
__device__ float g_h2[(size_t)NN * F];

// ================= CSR build =================
__global__ void k_zero() {
    int i = blockIdx.x * blockDim.x + threadIdx.x;
    if (i < NN) { g_cnt[i] = 0; g_fill[i] = 0; }
}
__global__ void k_hist(const int* __restrict__ dst) {
    int e = blockIdx.x * blockDim.x + threadIdx.x;
    if (e < EE) atomicAdd(&g_cnt[dst[e]], 1);
}
// warp-shuffle block scan, 1024 threads, chunked over NN
__global__ void k_scan() {
    __shared__ int wsum[32];
    const int tid = threadIdx.x, lane = tid & 31, wid = tid >> 5;
    int carry = 0;
    for (int base = 0; base < NN; base += 1024) {
        int idx  = base + tid;
        int orig = (idx < NN) ? g_cnt[idx] : 0;
        int x = orig;
#pragma unroll
        for (int off = 1; off < 32; off <<= 1) {
            int y = __shfl_up_sync(0xffffffffu, x, off);
            if (lane >= off) x += y;
        }
        if (lane == 31) wsum[wid] = x;
        __syncthreads();
        if (wid == 0) {
            int s = wsum[lane];
#pragma unroll
            for (int off = 1; off < 32; off <<= 1) {
                int y = __shfl_up_sync(0xffffffffu, s, off);
                if (lane >= off) s += y;
            }
            wsum[lane] = s;
        }
        __syncthreads();
        int pre = carry + (wid ? wsum[wid - 1] : 0);
        if (idx < NN) g_rowptr[idx] = pre + x - orig;
        carry += wsum[31];
        __syncthreads();
    }
    if (tid == 0) g_rowptr[NN] = carry;
}
__global__ void k_scatter(const int* __restrict__ src, const int* __restrict__ dst,
                          const float* __restrict__ ew) {
    int e = blockIdx.x * blockDim.x + threadIdx.x;
    if (e < EE) {
        int d = dst[e];
        int p = g_rowptr[d] + atomicAdd(&g_fill[d], 1);
        g_csrc[p] = src[e];
        g_cew[p]  = ew[e];
    }
}

// ================= aggregation (gather, warp per node) =================
__global__ void k_agg(const float* __restrict__ hin) {
    int v    = (blockIdx.x * blockDim.x + threadIdx.x) >> 5;
    int lane = threadIdx.x & 31;
    if (v >= NN) return;
    int s0 = g_rowptr[v], s1 = g_rowptr[v + 1];
    float4 acc = make_float4(0.f, 0.f, 0.f, 0.f);
    int i = s0;
    for (; i + 1 < s1; i += 2) {
        int   sa = g_csrc[i],  sb = g_csrc[i + 1];
        float wa = g_cew[i],   wb = g_cew[i + 1];
        const float4 A = *reinterpret_cast<const float4*>(hin + (size_t)sa * F + lane * 4);
        const float4 B = *reinterpret_cast<const float4*>(hin + (size_t)sb * F + lane * 4);
        acc.x += wa * A.x + wb * B.x;
        acc.y += wa * A.y + wb * B.y;
        acc.z += wa * A.z + wb * B.z;
        acc.w += wa * A.w + wb * B.w;
    }
    if (i < s1) {
        int   s  = g_csrc[i];
        float wt = g_cew[i];
        const float4 hv = *reinterpret_cast<const float4*>(hin + (size_t)s * F + lane * 4);
        acc.x += wt * hv.x; acc.y += wt * hv.y;
        acc.z += wt * hv.z; acc.w += wt * hv.w;
    }
    int deg = s1 - s0;
    float invd = 1.0f / (float)(deg > 1 ? deg : 1);
    acc.x *= invd; acc.y *= invd; acc.z *= invd; acc.w *= invd;
    *reinterpret_cast<float4*>(g_neigh + (size_t)v * F + lane * 4) = acc;
}

// ================= packed-f32x2 helpers =================
__device__ __forceinline__ void fma2(unsigned long long& d,
                                     unsigned long long a, unsigned long long b) {
    asm("fma.rn.f32x2 %0, %1, %2, %3;" : "=l"(d) : "l"(a), "l"(b), "l"(d));
}
__device__ __forceinline__ float2 unpack2(unsigned long long v) {
    float2 f;
    asm("mov.b64 {%0, %1}, %2;" : "=f"(f.x), "=f"(f.y) : "l"(v));
    return f;
}

// ================= fused SAGE GEMM (f32x2, transposed weights) =================
// 256 threads = 8 warps; block tile = 64 nodes.
//   warp w : nodes 8w..8w+7 (whole warp shares nodes -> h LDS broadcast)
//   lane l : features j = l + 32m, m = 0..3
// acc2[i][m] = f32x2 packed along K (even/odd k partial sums).
// Weights transposed to s_w[j*WPAD + k]; LDS.128 bank-group = 4*lane: conflict-free.
// Two sequential passes (self then neigh) reuse s_w and s_t.
// DOT variant fuses the final projection (w2 dot + b2) into the epilogue.
template <bool HN, bool DOT>
__global__ void __launch_bounds__(256, 2)
k_sage(const float* __restrict__ hin, const float* __restrict__ ws,
       const float* __restrict__ wn, const float* __restrict__ b,
       float* __restrict__ hout,
       const float* __restrict__ w2, const float* __restrict__ b2,
       float* __restrict__ outv) {
    extern __shared__ float sm[];
    float* s_w = sm;                 // [128][WPAD] transposed
    float* s_t = sm + F * WPAD;      // [64][128] node tile

    const int tid  = threadIdx.x;
    const int lane = tid & 31;
    const int wid  = tid >> 5;
    const int nodeBase = blockIdx.x * 64;
    const int n0 = 8 * wid;

    unsigned long long acc2[8][4];
#pragma unroll
    for (int i = 0; i < 8; i++)
#pragma unroll
        for (int m = 0; m < 4; m++) acc2[i][m] = 0ull;

    const float* s_trow[8];
#pragma unroll
    for (int i = 0; i < 8; i++) s_trow[i] = s_t + (n0 + i) * F;
    const float* s_wrow[4];
#pragma unroll
    for (int m = 0; m < 4; m++) s_wrow[m] = s_w + (lane + 32 * m) * WPAD;

    for (int pass = 0; pass < (HN ? 2 : 1); pass++) {
        const float* W    = (pass == 0) ? ws : wn;
        const float* srcp = (pass == 0) ? hin : g_neigh;
        if (pass) __syncthreads();          // everyone done reading prev pass smem

        // ---- transpose weights into s_w: task = (m, k0) pair per warp ----
        for (int task = wid; task < 128; task += 8) {
            int m  = task & 3;
            int k0 = (task >> 2) * 4;
            int j  = m * 32 + lane;
            float4 v;
            v.x = W[(k0 + 0) * F + j];
            v.y = W[(k0 + 1) * F + j];
            v.z = W[(k0 + 2) * F + j];
            v.w = W[(k0 + 3) * F + j];
            *reinterpret_cast<float4*>(s_w + j * WPAD + k0) = v;   // conflict-free
        }
        // ---- stage node tile ----
        for (int t = tid; t < 64 * 32; t += 256) {
            int n = t >> 5, q = (t & 31) * 4;
            int v = nodeBase + n;
            float4 hv = make_float4(0.f, 0.f, 0.f, 0.f);
            if (v < NN) hv = *reinterpret_cast<const float4*>(srcp + (size_t)v * F + q);
            *reinterpret_cast<float4*>(s_t + n * F + q) = hv;
        }
        __syncthreads();

        // ---- main loop: 32 chunks of 4 k ----
#pragma unroll 2
        for (int c = 0; c < 32; c++) {
            ulonglong2 w[4];
#pragma unroll
            for (int m = 0; m < 4; m++)
                w[m] = *reinterpret_cast<const ulonglong2*>(s_wrow[m] + c * 4);
#pragma unroll
            for (int i = 0; i < 8; i++) {
                ulonglong2 h = *reinterpret_cast<const ulonglong2*>(s_trow[i] + c * 4);
#pragma unroll
                for (int m = 0; m < 4; m++) {
                    fma2(acc2[i][m], h.x, w[m].x);
                    fma2(acc2[i][m], h.y, w[m].y);
                }
            }
        }
    }

    // ---- epilogue ----
    float bj[4];
#pragma unroll
    for (int m = 0; m < 4; m++) bj[m] = b[lane + 32 * m];

    if (!DOT) {
#pragma unroll
        for (int i = 0; i < 8; i++) {
            int v = nodeBase + n0 + i;
            if (v < NN) {
#pragma unroll
                for (int m = 0; m < 4; m++) {
                    float2 f = unpack2(acc2[i][m]);
                    hout[(size_t)v * F + lane + 32 * m] = fmaxf(f.x + f.y + bj[m], 0.f);
                }
            }
        }
    } else {
        float w2j[4];
#pragma unroll
        for (int m = 0; m < 4; m++) w2j[m] = w2[lane + 32 * m];
        float bias2 = b2[0];
#pragma unroll
        for (int i = 0; i < 8; i++) {
            float s = 0.f;
#pragma unroll
            for (int m = 0; m < 4; m++) {
                float2 f = unpack2(acc2[i][m]);
                s += fmaxf(f.x + f.y + bj[m], 0.f) * w2j[m];
            }
#pragma unroll
            for (int o = 16; o; o >>= 1) s += __shfl_xor_sync(0xffffffffu, s, o);
            int v = nodeBase + n0 + i;
            if (lane == 0 && v < NN) outv[v] = s + bias2;
        }
    }
}

// ================= launch =================
extern "C" void kernel_launch(void* const* d_in, const int* in_sizes, int n_in,
                              void* d_out, int out_size) {
    const float* inputs = (const float*)d_in[0];
    const float* ew     = (const float*)d_in[1];
    const int*   src    = (const int*)d_in[2];
    const int*   dst    = (const int*)d_in[3];
    const float* ws1 = (const float*)d_in[4];
    const float* wn1 = (const float*)d_in[5];
    const float* b1  = (const float*)d_in[6];
    const float* ws2 = (const float*)d_in[7];
    const float* wn2 = (const float*)d_in[8];
    const float* b2  = (const float*)d_in[9];
    const float* ws3 = (const float*)d_in[10];
    const float* wn3 = (const float*)d_in[11];
    const float* b3  = (const float*)d_in[12];
    const float* wl1 = (const float*)d_in[13];
    const float* bl1 = (const float*)d_in[14];
    const float* wl2 = (const float*)d_in[15];
    const float* bl2 = (const float*)d_in[16];
    float* out = (float*)d_out;

    float *h1, *h2;
    cudaGetSymbolAddress((void**)&h1, g_h1);
    cudaGetSymbolAddress((void**)&h2, g_h2);

    // smem: weight [128][WPAD] + node tile [64][128] = 100352 B -> 2 blocks/SM
    const size_t smem = (size_t)(F * WPAD + 64 * F) * sizeof(float);
    cudaFuncSetAttribute((const void*)k_sage<true,  false>, cudaFuncAttributeMaxDynamicSharedMemorySize, (int)smem);
    cudaFuncSetAttribute((const void*)k_sage<false, true>,  cudaFuncAttributeMaxDynamicSharedMemorySize, (int)smem);

    const int TB = 256;
    k_zero<<<(NN + TB - 1) / TB, TB>>>();
    k_hist<<<(EE + TB - 1) / TB, TB>>>(dst);
    k_scan<<<1, 1024>>>();
    k_scatter<<<(EE + TB - 1) / TB, TB>>>(src, dst, ew);

    const int aggBlocks  = (NN * 32 + TB - 1) / TB;
    const int sageBlocks = (NN + 63) / 64;          // 782

    // layer 1
    k_agg<<<aggBlocks, TB>>>(inputs);
    k_sage<true, false><<<sageBlocks, 256, smem>>>(inputs, ws1, wn1, b1, h1,
                                                   nullptr, nullptr, nullptr);
    // layer 2
    k_agg<<<aggBlocks, TB>>>(h1);
    k_sage<true, false><<<sageBlocks, 256, smem>>>(h1, ws2, wn2, b2, h2,
                                                   nullptr, nullptr, nullptr);
    // layer 3
    k_agg<<<aggBlocks, TB>>>(h2);
    k_sage<true, false><<<sageBlocks, 256, smem>>>(h2, ws3, wn3, b3, h1,
                                                   nullptr, nullptr, nullptr);
    // lin1 + lin2 fused (self path + dot epilogue)
    k_sage<false, true><<<sageBlocks, 256, smem>>>(h1, wl1, nullptr, bl1, nullptr,
                                                   wl2, bl2, out);
}